// round 14
// baseline (speedup 1.0000x reference)
#include <cuda_runtime.h>
#include <cuda_fp16.h>
#include <math.h>
#include <stdint.h>

#define NH   4
#define NN   4096
#define FIN  512
#define FOUT 128
#define LALPHA 0.2f
#define CH   128
#define NC   (NN / CH)

typedef unsigned long long u64;
typedef unsigned int u32;

// ---------------- scratch ----------------
__device__ float g_ham[NH * FIN * FOUT];
__device__ float g_fs[NH * NN];
__device__ float4 g_cp[NH * NN];                 // (fd, exp(fd), exp(0.2fd), 0)
__device__ u32 g_maxkey[NH];
__device__ u32 g_adjb[NN * (NN / 32)];
__device__ __half g_hT[NH * FOUT * NN];          // [h][o][m] fp16

// ---------------- helpers ----------------
__device__ __forceinline__ u64 pack2(float lo, float hi) {
    u64 r; asm("mov.b64 %0, {%1, %2};" : "=l"(r) : "f"(lo), "f"(hi)); return r;
}
__device__ __forceinline__ void fma2(u64& d, u64 a, u64 b) {
    asm("fma.rn.f32x2 %0, %1, %2, %0;" : "+l"(d) : "l"(a), "l"(b));
}
__device__ __forceinline__ float2 unpack2(u64 v) {
    float lo, hi; asm("mov.b64 {%0, %1}, %2;" : "=f"(lo), "=f"(hi) : "l"(v));
    return make_float2(lo, hi);
}
__device__ __forceinline__ u32 smem_u32(const void* p) {
    u32 a; asm("{ .reg .u64 t; cvta.to.shared.u64 t, %1; cvt.u32.u64 %0, t; }" : "=r"(a) : "l"(p));
    return a;
}
__device__ __forceinline__ u32 fkey(float f) {
    u32 b = __float_as_uint(f);
    return (b & 0x80000000u) ? ~b : (b | 0x80000000u);
}
__device__ __forceinline__ float fdec(u32 k) {
    u32 b = (k & 0x80000000u) ? (k & 0x7FFFFFFFu) : ~k;
    return __uint_as_float(b);
}
#define SW128(x) ((x) ^ (((x) >> 3) & 0x70))

#define LDM4(d, addr) \
    asm volatile("ldmatrix.sync.aligned.m8n8.x4.shared.b16 {%0,%1,%2,%3}, [%4];" \
        : "=r"((d)[0]), "=r"((d)[1]), "=r"((d)[2]), "=r"((d)[3]) : "r"(addr))

#define MMA_F16(c, a, b0, b1) \
    asm volatile("mma.sync.aligned.m16n8k16.row.col.f32.f16.f16.f32 " \
        "{%0,%1,%2,%3},{%4,%5,%6,%7},{%8,%9},{%0,%1,%2,%3};" \
        : "+f"((c)[0]), "+f"((c)[1]), "+f"((c)[2]), "+f"((c)[3]) \
        : "r"((a)[0]), "r"((a)[1]), "r"((a)[2]), "r"((a)[3]), "r"(b0), "r"(b1))

#define CPASYNC16(dst, src) \
    asm volatile("cp.async.cg.shared.global [%0], [%1], 16;" :: "r"(dst), "l"(src))

#define BAR_SYNC(id, cnt)   asm volatile("bar.sync %0, %1;" :: "r"(id), "r"(cnt) : "memory")
#define BAR_ARRIVE(id, cnt) asm volatile("bar.arrive %0, %1;" :: "r"(id), "r"(cnt) : "memory")

#define ONESF 0x3C003C00u   // fp16x2 (1.0, 1.0)

// ---------------- kernel 1: hamilton + adj pack + maxkey reset ----------------
__global__ void prep_kernel(const float* __restrict__ W, const int* __restrict__ adj) {
    if (blockIdx.x < 1024) {
        int idx = blockIdx.x * 256 + threadIdx.x;
        if (idx < NH) g_maxkey[idx] = 0u;
        int o = idx & 127, f = (idx >> 7) & 511, h = idx >> 16;
        int q = f >> 7, fi = f & 127, p = o >> 5, oi = o & 31;
        const int negmask[4] = {0, 9, 3, 5};
        float sgn = ((negmask[q] >> p) & 1) ? -1.f : 1.f;
        g_ham[idx] = sgn * W[h * (128 * 128) + fi * 128 + (q ^ p) * 32 + oi];
    } else {
        int idx = (blockIdx.x - 1024) * 256 + threadIdx.x;   // word-pair index, < 262144
        const int4* p = (const int4*)adj + (size_t)idx * 16;
        int4 vv[16];
#pragma unroll
        for (int i = 0; i < 16; i++) vv[i] = p[i];
        u32 w0 = 0, w1 = 0;
#pragma unroll
        for (int i = 0; i < 8; i++) {
            w0 |= ((u32)vv[i].x & 1u) << (4 * i);
            w0 |= ((u32)vv[i].y & 1u) << (4 * i + 1);
            w0 |= ((u32)vv[i].z & 1u) << (4 * i + 2);
            w0 |= ((u32)vv[i].w & 1u) << (4 * i + 3);
            w1 |= ((u32)vv[8 + i].x & 1u) << (4 * i);
            w1 |= ((u32)vv[8 + i].y & 1u) << (4 * i + 1);
            w1 |= ((u32)vv[8 + i].z & 1u) << (4 * i + 2);
            w1 |= ((u32)vv[8 + i].w & 1u) << (4 * i + 3);
        }
        *(uint2*)&g_adjb[2 * idx] = make_uint2(w0, w1);
    }
}

// ---------------- kernel 2: h = x @ hamilton, fused epilogue ----------------
__global__ __launch_bounds__(128) void gemm_h_kernel(const float* __restrict__ x,
                                                     const float* __restrict__ a) {
    __shared__ float Xs[64][33];
    __shared__ float Hs[32][132];
    int t = threadIdx.x;
    int h = blockIdx.y, n0 = blockIdx.x * 64;
    int tx = t & 15, ty = t >> 4;
    u64 acc2[8][4];
#pragma unroll
    for (int i = 0; i < 8; i++)
#pragma unroll
        for (int j = 0; j < 4; j++) acc2[i][j] = 0ull;
    const float* hamb = g_ham + (size_t)h * (FIN * FOUT);

    for (int f0 = 0; f0 < FIN; f0 += 32) {
        __syncthreads();
#pragma unroll
        for (int i = 0; i < 16; i++) {
            int idx = t + i * 128;
            int r = idx >> 5, c = idx & 31;
            Xs[r][c] = x[(size_t)(n0 + r) * FIN + f0 + c];
        }
#pragma unroll
        for (int i = 0; i < 8; i++) {
            int idx4 = t + i * 128;
            int k = idx4 >> 5, c4 = idx4 & 31;
            *(float4*)&Hs[k][c4 * 4] = *(const float4*)(hamb + (size_t)(f0 + k) * FOUT + c4 * 4);
        }
        __syncthreads();
#pragma unroll
        for (int k = 0; k < 32; k++) {
            ulonglong2 q0 = *(const ulonglong2*)&Hs[k][tx * 8];
            ulonglong2 q1 = *(const ulonglong2*)&Hs[k][tx * 8 + 4];
            u64 bp[4] = {q0.x, q0.y, q1.x, q1.y};
#pragma unroll
            for (int i = 0; i < 8; i++) {
                float av = Xs[ty * 8 + i][k];
                u64 ap = pack2(av, av);
#pragma unroll
                for (int j = 0; j < 4; j++) fma2(acc2[i][j], ap, bp[j]);
            }
        }
    }

    float v[8][8];
#pragma unroll
    for (int i = 0; i < 8; i++)
#pragma unroll
        for (int j = 0; j < 4; j++) {
            float2 pr = unpack2(acc2[i][j]);
            v[i][2 * j] = pr.x;
            v[i][2 * j + 1] = pr.y;
        }

#pragma unroll
    for (int j = 0; j < 8; j++) {
        int o = tx * 8 + j;
        u32 hh[4];
#pragma unroll
        for (int q = 0; q < 4; q++) {
            __half2 hv = __floats2half2_rn(v[2 * q][j], v[2 * q + 1][j]);
            hh[q] = *(u32*)&hv;
        }
        size_t off = ((size_t)h * FOUT + o) * NN + n0 + ty * 8;
        *(uint4*)(g_hT + off) = make_uint4(hh[0], hh[1], hh[2], hh[3]);
    }

    float p1[8], p2[8];
    const float* ah = a + h * 256;
#pragma unroll
    for (int i = 0; i < 8; i++) { p1[i] = 0.f; p2[i] = 0.f; }
#pragma unroll
    for (int j = 0; j < 8; j++) {
        float asj = ah[tx * 8 + j];
        float adj_ = ah[128 + tx * 8 + j];
#pragma unroll
        for (int i = 0; i < 8; i++) {
            p1[i] += v[i][j] * asj;
            p2[i] += v[i][j] * adj_;
        }
    }
#pragma unroll
    for (int off = 8; off; off >>= 1) {
#pragma unroll
        for (int i = 0; i < 8; i++) {
            p1[i] += __shfl_xor_sync(0xffffffffu, p1[i], off);
            p2[i] += __shfl_xor_sync(0xffffffffu, p2[i], off);
        }
    }
    if (tx == 0) {
        float mx = -1e30f;
#pragma unroll
        for (int i = 0; i < 8; i++) {
            int idx = h * NN + n0 + ty * 8 + i;
            float s1 = p1[i], s2 = p2[i];
            g_fs[idx] = s1;
            g_cp[idx] = make_float4(s2, expf(s2), expf(LALPHA * s2), 0.f);
            mx = fmaxf(mx, s2);
        }
        atomicMax(&g_maxkey[h], fkey(mx));
    }
}

// ---------------- kernel 3: warp-specialized fp16 HMMA attention ----------------
// 512 threads: warps 0-7 consumers, warps 8-15 producers.
// Chunk = 128 m-cols as TWO 64-col sub-tiles. 3 stages x 64 KB.
// Stage layout: Q0 16K | Q1 16K | V0 16K | V1 16K
#define SM_RS    0                         // 2 x 128 floats
#define SM_PRM   1024                      // 3 stages * 128 * float4 = 6144
#define SM_TILES 8192
#define STAGE_SZ 65536
#define SM_TOTAL (SM_TILES + 3 * STAGE_SZ)

#define BFULL 1      // ids 1..3
#define BEMPT 4      // ids 4..6
#define BPROD 7

__global__ __launch_bounds__(512, 1) void attn_mma_kernel(float* __restrict__ out) {
    extern __shared__ char smem[];
    u32 sb = smem_u32(smem);
    float* rs = (float*)(smem + SM_RS);
    float4* prm_all = (float4*)(smem + SM_PRM);

    int t = threadIdx.x;
    int h = blockIdx.y, n0 = blockIdx.x * 128, hN = h * NN;

    if (t < 256) {
        // ================= CONSUMERS =================
        int wid = t >> 5, L = t & 31;
        int wr = wid & 3, wc = wid >> 2;
        float acc[2][8][4];
        float accr[2][4];
#pragma unroll
        for (int mt = 0; mt < 2; mt++) {
#pragma unroll
            for (int n8 = 0; n8 < 8; n8++)
#pragma unroll
                for (int e = 0; e < 4; e++) acc[mt][n8][e] = 0.f;
#pragma unroll
            for (int e = 0; e < 4; e++) accr[mt][e] = 0.f;
        }

        u32 xorx = (u32)((L & 7) << 4);
        u32 aRow = (u32)((wr * 32 + (L & 15)) * 128);
        u32 aHalf = (u32)((L >> 4) * 16);
        u32 bRow = (u32)((wc * 64 + ((L >> 4) & 1) * 8 + (L & 7)) * 128);
        u32 bHalf = (u32)(((L >> 3) & 1) * 16);

        int s = 0;
        for (int c = 0; c < NC; c++) {
            BAR_SYNC(BFULL + s, 512);
            u32 stage = sb + SM_TILES + s * STAGE_SZ;
#pragma unroll
            for (int half = 0; half < 2; half++) {
                u32 aQ = stage + (u32)(half * 16384);
                u32 bV = stage + 32768 + (u32)(half * 16384);
                bool doR = (half == 0) == (wc == 0);   // balanced rowsum split
#pragma unroll
                for (int kt = 0; kt < 4; kt++) {
                    u32 aCol = ((u32)(kt * 32) + aHalf) ^ xorx;
                    u32 bCol = ((u32)(kt * 32) + bHalf) ^ xorx;
                    u32 ah[2][4];
#pragma unroll
                    for (int mt = 0; mt < 2; mt++)
                        LDM4(ah[mt], aQ + aRow + (u32)(mt * 2048) + aCol);
                    if (doR) {
                        MMA_F16(accr[0], ah[0], ONESF, ONESF);
                        MMA_F16(accr[1], ah[1], ONESF, ONESF);
                    }
#pragma unroll
                    for (int ng = 0; ng < 4; ng++) {
                        u32 bv[4];
                        LDM4(bv, bV + bRow + (u32)(ng * 2048) + bCol);
#pragma unroll
                        for (int e = 0; e < 2; e++)
#pragma unroll
                            for (int mt = 0; mt < 2; mt++)
                                MMA_F16(acc[mt][2 * ng + e], ah[mt], bv[2 * e], bv[2 * e + 1]);
                    }
                }
            }
            BAR_ARRIVE(BEMPT + s, 512);
            if (++s == 3) s = 0;
        }

        // publish partial row sums
        if ((L & 3) == 0) {
            int gid = L >> 2;
            float* rdst = rs + wc * 128;
#pragma unroll
            for (int mt = 0; mt < 2; mt++) {
                rdst[wr * 32 + mt * 16 + gid]     = accr[mt][0];
                rdst[wr * 32 + mt * 16 + 8 + gid] = accr[mt][2];
            }
        }
        __syncthreads();

        int gid = L >> 2, tid = L & 3;
#pragma unroll
        for (int mt = 0; mt < 2; mt++) {
#pragma unroll
            for (int half = 0; half < 2; half++) {
                int rt = wr * 32 + mt * 16 + half * 8 + gid;
                float inv = 1.f / (rs[rt] + rs[128 + rt]);
                float* op = out + (size_t)(n0 + rt) * (NH * FOUT) + h * FOUT + wc * 64 + tid * 2;
#pragma unroll
                for (int n8 = 0; n8 < 8; n8++) {
                    float v0 = acc[mt][n8][half * 2] * inv;
                    float v1 = acc[mt][n8][half * 2 + 1] * inv;
                    v0 = (v0 > 0.f) ? v0 : expm1f(v0);
                    v1 = (v1 > 0.f) ? v1 : expm1f(v1);
                    *(float2*)(op + n8 * 8) = make_float2(v0, v1);
                }
            }
        }
    } else {
        // ================= PRODUCERS =================
        // Thread (r, ch): row r of sub-tile ch (64 cols) per chunk.
        int pt = t - 256;            // 0..255
        int r = pt >> 1, ch = pt & 1;
        float fsn = g_fs[hN + n0 + r];
        float maxfd = fdec(g_maxkey[h]);
        float emx = expf(maxfd), emxa = expf(LALPHA * maxfd);
        float En = expf(-0.8f * fsn);
        float bnd = fmaxf(emx, En * emxa);
        float Sn = (bnd > 30000.f) ? (30000.f / bnd) : 1.f;
        float SnEn = Sn * En;

        // adj words for this thread's 64 cols: uint2 at word offset 4c + 2ch
        const uint2* aj2 = (const uint2*)(g_adjb + (size_t)(n0 + r) * (NN / 32)) + ch;
        const __half* hT = g_hT + (size_t)h * FOUT * NN;
        const float4* gcp = g_cp + hN;

        int s = 0;
        for (int c = 0; c < NC; c++) {
            int m0 = c * CH;

            // ---- prefetch before empty-wait ----
            uint2 aw2 = aj2[2 * c];
            float4 prv_stage = make_float4(0.f, 0.f, 0.f, 0.f);
            if (pt < 128) prv_stage = gcp[m0 + pt];

            if (c >= 3) BAR_SYNC(BEMPT + s, 512);

            u32 stage = sb + SM_TILES + s * STAGE_SZ;
            // V loads: 8 cp.async per thread (2 sub-tiles x 16 KB)
#pragma unroll
            for (int i = 0; i < 8; i++) {
                int idx = pt + i * 256;            // 0..2047
                int vh = idx >> 10;                // sub-tile
                int idx2 = idx & 1023;
                int o = idx2 >> 3, seg = idx2 & 7;
                u32 dst = stage + 32768 + (u32)(vh * 16384) + SW128((u32)(o * 128 + seg * 16));
                CPASYNC16(dst, hT + (size_t)o * NN + m0 + vh * 64 + seg * 8);
            }
            asm volatile("cp.async.commit_group;" ::: "memory");

            if (pt < 128) prm_all[s * 128 + pt] = prv_stage;
            BAR_SYNC(BPROD, 256);

            const float4* prm = prm_all + s * 128 + ch * 64;
            char* Q = smem + SM_TILES + s * STAGE_SZ + ch * 16384;
#pragma unroll
            for (int jj = 0; jj < 64; jj += 8) {
                u32 bits = ((jj < 32) ? aw2.x : aw2.y) >> (jj & 31);
                u32 hp[4];
#pragma unroll
                for (int q = 0; q < 4; q++) {
                    float p[2];
#pragma unroll
                    for (int e = 0; e < 2; e++) {
                        int j = q * 2 + e;
                        float4 prv = prm[jj + j];
                        float s1 = fsn + prv.x;
                        float mm = (s1 > 0.f) ? prv.y : prv.z;
                        float cc = (s1 > 0.f) ? Sn : SnEn;
                        p[e] = ((bits >> j) & 1) ? (mm * cc) : 0.f;
                    }
                    __half2 hv = __floats2half2_rn(p[0], p[1]);
                    hp[q] = *(u32*)&hv;
                }
                u32 sw = SW128((u32)(r * 128 + jj * 2));
                *(uint4*)(Q + sw) = make_uint4(hp[0], hp[1], hp[2], hp[3]);
            }

            asm volatile("cp.async.wait_group 0;" ::: "memory");
            BAR_ARRIVE(BFULL + s, 512);
            if (++s == 3) s = 0;
        }
        __syncthreads();
    }
}

// ---------------- launch ----------------
extern "C" void kernel_launch(void* const* d_in, const int* in_sizes, int n_in,
                              void* d_out, int out_size) {
    const float* x  = (const float*)d_in[0];
    const int* adj  = (const int*)d_in[1];
    const float* W  = (const float*)d_in[2];
    const float* a  = (const float*)d_in[3];
    float* out = (float*)d_out;

    cudaFuncSetAttribute(attn_mma_kernel, cudaFuncAttributeMaxDynamicSharedMemorySize, SM_TOTAL);

    prep_kernel<<<2048, 256>>>(W, adj);
    gemm_h_kernel<<<dim3(NN / 64, NH), 128>>>(x, a);
    attn_mma_kernel<<<dim3(NN / 128, NH), 512, SM_TOTAL>>>(out);
}

// round 15
// speedup vs baseline: 1.0477x; 1.0477x over previous
#include <cuda_runtime.h>
#include <cuda_fp16.h>
#include <math.h>
#include <stdint.h>

#define NH   4
#define NN   4096
#define FIN  512
#define FOUT 128
#define LALPHA 0.2f
#define CH   64
#define NC   (NN / CH)

typedef unsigned long long u64;
typedef unsigned int u32;

// ---------------- scratch ----------------
__device__ float g_ham[NH * FIN * FOUT];
__device__ float g_fs[NH * NN];
__device__ float4 g_cp[NH * NN];                 // (fd, exp(fd), exp(0.2fd), 0)
__device__ u32 g_maxkey[NH];
__device__ u32 g_adjb[NN * (NN / 32)];
__device__ __half g_hT[NH * FOUT * NN];          // [h][o][m] fp16

// ---------------- helpers ----------------
__device__ __forceinline__ u64 pack2(float lo, float hi) {
    u64 r; asm("mov.b64 %0, {%1, %2};" : "=l"(r) : "f"(lo), "f"(hi)); return r;
}
__device__ __forceinline__ void fma2(u64& d, u64 a, u64 b) {
    asm("fma.rn.f32x2 %0, %1, %2, %0;" : "+l"(d) : "l"(a), "l"(b));
}
__device__ __forceinline__ float2 unpack2(u64 v) {
    float lo, hi; asm("mov.b64 {%0, %1}, %2;" : "=f"(lo), "=f"(hi) : "l"(v));
    return make_float2(lo, hi);
}
__device__ __forceinline__ u32 smem_u32(const void* p) {
    u32 a; asm("{ .reg .u64 t; cvta.to.shared.u64 t, %1; cvt.u32.u64 %0, t; }" : "=r"(a) : "l"(p));
    return a;
}
__device__ __forceinline__ u32 fkey(float f) {
    u32 b = __float_as_uint(f);
    return (b & 0x80000000u) ? ~b : (b | 0x80000000u);
}
__device__ __forceinline__ float fdec(u32 k) {
    u32 b = (k & 0x80000000u) ? (k & 0x7FFFFFFFu) : ~k;
    return __uint_as_float(b);
}
#define SW128(x) ((x) ^ (((x) >> 3) & 0x70))

#define LDM4(d, addr) \
    asm volatile("ldmatrix.sync.aligned.m8n8.x4.shared.b16 {%0,%1,%2,%3}, [%4];" \
        : "=r"((d)[0]), "=r"((d)[1]), "=r"((d)[2]), "=r"((d)[3]) : "r"(addr))

#define MMA_F16(c, a, b0, b1) \
    asm volatile("mma.sync.aligned.m16n8k16.row.col.f32.f16.f16.f32 " \
        "{%0,%1,%2,%3},{%4,%5,%6,%7},{%8,%9},{%0,%1,%2,%3};" \
        : "+f"((c)[0]), "+f"((c)[1]), "+f"((c)[2]), "+f"((c)[3]) \
        : "r"((a)[0]), "r"((a)[1]), "r"((a)[2]), "r"((a)[3]), "r"(b0), "r"(b1))

#define CPASYNC16(dst, src) \
    asm volatile("cp.async.cg.shared.global [%0], [%1], 16;" :: "r"(dst), "l"(src))

#define BAR_SYNC(id, cnt)   asm volatile("bar.sync %0, %1;" :: "r"(id), "r"(cnt) : "memory")
#define BAR_ARRIVE(id, cnt) asm volatile("bar.arrive %0, %1;" :: "r"(id), "r"(cnt) : "memory")

#define ONESF 0x3C003C00u   // fp16x2 (1.0, 1.0)

// ---------------- kernel 1: hamilton + adj pack + maxkey reset ----------------
// blocks [0, 1024): hamilton. blocks [1024, 2048): adj bit-pack (262144 word-pairs).
// __launch_bounds__(256, 2): allow ~128 regs so ptxas keeps all 16 int4 loads in flight.
__global__ __launch_bounds__(256, 2) void prep_kernel(const float* __restrict__ W,
                                                      const int* __restrict__ adj) {
    if (blockIdx.x < 1024) {
        int idx = blockIdx.x * 256 + threadIdx.x;
        if (idx < NH) g_maxkey[idx] = 0u;
        int o = idx & 127, f = (idx >> 7) & 511, h = idx >> 16;
        int q = f >> 7, fi = f & 127, p = o >> 5, oi = o & 31;
        const int negmask[4] = {0, 9, 3, 5};
        float sgn = ((negmask[q] >> p) & 1) ? -1.f : 1.f;
        g_ham[idx] = sgn * W[h * (128 * 128) + fi * 128 + (q ^ p) * 32 + oi];
    } else {
        int idx = (blockIdx.x - 1024) * 256 + threadIdx.x;   // word-pair index, < 262144
        const int4* p = (const int4*)adj + (size_t)idx * 16;
        int4 vv[16];
#pragma unroll
        for (int i = 0; i < 16; i++) vv[i] = p[i];
        u32 w0 = 0, w1 = 0;
#pragma unroll
        for (int i = 0; i < 8; i++) {
            w0 |= ((u32)vv[i].x & 1u) << (4 * i);
            w0 |= ((u32)vv[i].y & 1u) << (4 * i + 1);
            w0 |= ((u32)vv[i].z & 1u) << (4 * i + 2);
            w0 |= ((u32)vv[i].w & 1u) << (4 * i + 3);
            w1 |= ((u32)vv[8 + i].x & 1u) << (4 * i);
            w1 |= ((u32)vv[8 + i].y & 1u) << (4 * i + 1);
            w1 |= ((u32)vv[8 + i].z & 1u) << (4 * i + 2);
            w1 |= ((u32)vv[8 + i].w & 1u) << (4 * i + 3);
        }
        *(uint2*)&g_adjb[2 * idx] = make_uint2(w0, w1);
    }
}

// ---------------- kernel 2: h = x @ hamilton, fused epilogue ----------------
__global__ __launch_bounds__(128) void gemm_h_kernel(const float* __restrict__ x,
                                                     const float* __restrict__ a) {
    __shared__ float Xs[64][33];
    __shared__ float Hs[32][132];
    int t = threadIdx.x;
    int h = blockIdx.y, n0 = blockIdx.x * 64;
    int tx = t & 15, ty = t >> 4;
    u64 acc2[8][4];
#pragma unroll
    for (int i = 0; i < 8; i++)
#pragma unroll
        for (int j = 0; j < 4; j++) acc2[i][j] = 0ull;
    const float* hamb = g_ham + (size_t)h * (FIN * FOUT);

    for (int f0 = 0; f0 < FIN; f0 += 32) {
        __syncthreads();
#pragma unroll
        for (int i = 0; i < 16; i++) {
            int idx = t + i * 128;
            int r = idx >> 5, c = idx & 31;
            Xs[r][c] = x[(size_t)(n0 + r) * FIN + f0 + c];
        }
#pragma unroll
        for (int i = 0; i < 8; i++) {
            int idx4 = t + i * 128;
            int k = idx4 >> 5, c4 = idx4 & 31;
            *(float4*)&Hs[k][c4 * 4] = *(const float4*)(hamb + (size_t)(f0 + k) * FOUT + c4 * 4);
        }
        __syncthreads();
#pragma unroll
        for (int k = 0; k < 32; k++) {
            ulonglong2 q0 = *(const ulonglong2*)&Hs[k][tx * 8];
            ulonglong2 q1 = *(const ulonglong2*)&Hs[k][tx * 8 + 4];
            u64 bp[4] = {q0.x, q0.y, q1.x, q1.y};
#pragma unroll
            for (int i = 0; i < 8; i++) {
                float av = Xs[ty * 8 + i][k];
                u64 ap = pack2(av, av);
#pragma unroll
                for (int j = 0; j < 4; j++) fma2(acc2[i][j], ap, bp[j]);
            }
        }
    }

    float v[8][8];
#pragma unroll
    for (int i = 0; i < 8; i++)
#pragma unroll
        for (int j = 0; j < 4; j++) {
            float2 pr = unpack2(acc2[i][j]);
            v[i][2 * j] = pr.x;
            v[i][2 * j + 1] = pr.y;
        }

    // (1) transposed fp16 store of V = h^T
#pragma unroll
    for (int j = 0; j < 8; j++) {
        int o = tx * 8 + j;
        u32 hh[4];
#pragma unroll
        for (int q = 0; q < 4; q++) {
            __half2 hv = __floats2half2_rn(v[2 * q][j], v[2 * q + 1][j]);
            hh[q] = *(u32*)&hv;
        }
        size_t off = ((size_t)h * FOUT + o) * NN + n0 + ty * 8;
        *(uint4*)(g_hT + off) = make_uint4(hh[0], hh[1], hh[2], hh[3]);
    }

    // (2) f_src/f_dst dots + reduce
    float p1[8], p2[8];
    const float* ah = a + h * 256;
#pragma unroll
    for (int i = 0; i < 8; i++) { p1[i] = 0.f; p2[i] = 0.f; }
#pragma unroll
    for (int j = 0; j < 8; j++) {
        float asj = ah[tx * 8 + j];
        float adj_ = ah[128 + tx * 8 + j];
#pragma unroll
        for (int i = 0; i < 8; i++) {
            p1[i] += v[i][j] * asj;
            p2[i] += v[i][j] * adj_;
        }
    }
#pragma unroll
    for (int off = 8; off; off >>= 1) {
#pragma unroll
        for (int i = 0; i < 8; i++) {
            p1[i] += __shfl_xor_sync(0xffffffffu, p1[i], off);
            p2[i] += __shfl_xor_sync(0xffffffffu, p2[i], off);
        }
    }
    if (tx == 0) {
        float mx = -1e30f;
#pragma unroll
        for (int i = 0; i < 8; i++) {
            int idx = h * NN + n0 + ty * 8 + i;
            float s1 = p1[i], s2 = p2[i];
            g_fs[idx] = s1;
            g_cp[idx] = make_float4(s2, expf(s2), expf(LALPHA * s2), 0.f);
            mx = fmaxf(mx, s2);
        }
        atomicMax(&g_maxkey[h], fkey(mx));
    }
}

// ---------------- kernel 3: warp-specialized fp16 HMMA attention ----------------
// 512 threads: warps 0-7 consumers (MMA), warps 8-15 producers.
// 4 stages, each: Q 16K | V 16K
#define SM_RS    0
#define SM_PRM   512                       // 4 stages * 64 * float4 = 4096
#define SM_TILES 5120
#define STAGE_SZ 32768
#define SM_TOTAL (SM_TILES + 4 * STAGE_SZ)

#define BFULL 1      // ids 1..4
#define BEMPT 5      // ids 5..8
#define BPROD 9

__global__ __launch_bounds__(512, 1) void attn_mma_kernel(float* __restrict__ out) {
    extern __shared__ char smem[];
    u32 sb = smem_u32(smem);
    float* rs = (float*)(smem + SM_RS);
    float4* prm_all = (float4*)(smem + SM_PRM);

    int t = threadIdx.x;
    int h = blockIdx.y, n0 = blockIdx.x * 128, hN = h * NN;

    if (t < 256) {
        // ================= CONSUMERS =================
        int wid = t >> 5, L = t & 31;
        int wr = wid & 3, wc = wid >> 2;
        float acc[2][8][4];
        float accr[2][4];
#pragma unroll
        for (int mt = 0; mt < 2; mt++) {
#pragma unroll
            for (int n8 = 0; n8 < 8; n8++)
#pragma unroll
                for (int e = 0; e < 4; e++) acc[mt][n8][e] = 0.f;
#pragma unroll
            for (int e = 0; e < 4; e++) accr[mt][e] = 0.f;
        }

        u32 xorx = (u32)((L & 7) << 4);
        u32 aRow = (u32)((wr * 32 + (L & 15)) * 128);
        u32 aHalf = (u32)((L >> 4) * 16);
        u32 bRow = (u32)((wc * 64 + ((L >> 4) & 1) * 8 + (L & 7)) * 128);
        u32 bHalf = (u32)(((L >> 3) & 1) * 16);

        int s = 0;
        for (int c = 0; c < NC; c++) {
            BAR_SYNC(BFULL + s, 512);
            u32 stage = sb + SM_TILES + s * STAGE_SZ;
            u32 aQ = stage, bV = stage + 16384;
#pragma unroll
            for (int kt = 0; kt < 4; kt++) {
                u32 aCol = ((u32)(kt * 32) + aHalf) ^ xorx;
                u32 bCol = ((u32)(kt * 32) + bHalf) ^ xorx;
                u32 ah[2][4];
#pragma unroll
                for (int mt = 0; mt < 2; mt++)
                    LDM4(ah[mt], aQ + aRow + (u32)(mt * 2048) + aCol);
                if (wc == 0) {
                    // row sums via ones-fragment MMA (no loads)
                    MMA_F16(accr[0], ah[0], ONESF, ONESF);
                    MMA_F16(accr[1], ah[1], ONESF, ONESF);
                }
#pragma unroll
                for (int ng = 0; ng < 4; ng++) {
                    u32 bv[4];
                    LDM4(bv, bV + bRow + (u32)(ng * 2048) + bCol);
#pragma unroll
                    for (int e = 0; e < 2; e++)
#pragma unroll
                        for (int mt = 0; mt < 2; mt++)
                            MMA_F16(acc[mt][2 * ng + e], ah[mt], bv[2 * e], bv[2 * e + 1]);
                }
            }
            BAR_ARRIVE(BEMPT + s, 512);
            if (++s == 4) s = 0;
        }

        // publish row sums (all cols of ones-MMA result are equal; take c0/c2)
        if (wc == 0 && (L & 3) == 0) {
            int gid = L >> 2;
#pragma unroll
            for (int mt = 0; mt < 2; mt++) {
                rs[wr * 32 + mt * 16 + gid]     = accr[mt][0];
                rs[wr * 32 + mt * 16 + 8 + gid] = accr[mt][2];
            }
        }
        __syncthreads();

        int gid = L >> 2, tid = L & 3;
#pragma unroll
        for (int mt = 0; mt < 2; mt++) {
#pragma unroll
            for (int half = 0; half < 2; half++) {
                int rt = wr * 32 + mt * 16 + half * 8 + gid;
                float inv = 1.f / rs[rt];
                float* op = out + (size_t)(n0 + rt) * (NH * FOUT) + h * FOUT + wc * 64 + tid * 2;
#pragma unroll
                for (int n8 = 0; n8 < 8; n8++) {
                    float v0 = acc[mt][n8][half * 2] * inv;
                    float v1 = acc[mt][n8][half * 2 + 1] * inv;
                    v0 = (v0 > 0.f) ? v0 : expm1f(v0);
                    v1 = (v1 > 0.f) ? v1 : expm1f(v1);
                    *(float2*)(op + n8 * 8) = make_float2(v0, v1);
                }
            }
        }
    } else {
        // ================= PRODUCERS =================
        int pt = t - 256;            // 0..255
        int r = pt >> 1, ch = pt & 1;
        int cb = ch * 32;
        float fsn = g_fs[hN + n0 + r];
        // per-row fp16 overflow scale (inline)
        float maxfd = fdec(g_maxkey[h]);
        float emx = expf(maxfd), emxa = expf(LALPHA * maxfd);
        float En = expf(-0.8f * fsn);
        float bnd = fmaxf(emx, En * emxa);
        float Sn = (bnd > 30000.f) ? (30000.f / bnd) : 1.f;
        float SnEn = Sn * En;

        const u32* aj = g_adjb + (size_t)(n0 + r) * (NN / 32) + ch;
        const __half* hT = g_hT + (size_t)h * FOUT * NN;
        const float4* gcp = g_cp + hN;

        int s = 0;
        for (int c = 0; c < NC; c++) {
            int m0 = c * CH;

            // ---- prefetch BEFORE the empty-wait: latency drains inside the barrier ----
            u32 aw = aj[2 * c];                                     // packed adj word (L2)
            float4 prv_stage = make_float4(0.f, 0.f, 0.f, 0.f);
            if (pt < 64) prv_stage = gcp[m0 + pt];                  // params for staging

            if (c >= 4) BAR_SYNC(BEMPT + s, 512);

            // V tile loads: 4 cp.async per thread
            u32 vb = sb + SM_TILES + s * STAGE_SZ + 16384;
#pragma unroll
            for (int i = 0; i < 4; i++) {
                int idx = pt + i * 256;
                int o = idx >> 3, seg = idx & 7;
                u32 sw = SW128((u32)(o * 128 + seg * 16));
                CPASYNC16(vb + sw, hT + (size_t)o * NN + m0 + seg * 8);
            }
            asm volatile("cp.async.commit_group;" ::: "memory");

            if (pt < 64) prm_all[s * 64 + pt] = prv_stage;          // STS only
            BAR_SYNC(BPROD, 256);

            const float4* prm = prm_all + s * 64;
            char* Q = smem + SM_TILES + s * STAGE_SZ;
#pragma unroll
            for (int jj = 0; jj < 32; jj += 8) {
                u32 hp[4];
#pragma unroll
                for (int q = 0; q < 4; q++) {
                    float p[2];
#pragma unroll
                    for (int e = 0; e < 2; e++) {
                        int j = jj + q * 2 + e;
                        float4 prv = prm[cb + j];
                        float s1 = fsn + prv.x;
                        float mm = (s1 > 0.f) ? prv.y : prv.z;
                        float cc = (s1 > 0.f) ? Sn : SnEn;
                        float qv = mm * cc;
                        p[e] = ((aw >> j) & 1) ? qv : 0.f;
                    }
                    __half2 hv = __floats2half2_rn(p[0], p[1]);
                    hp[q] = *(u32*)&hv;
                }
                u32 sw = SW128((u32)(r * 128 + (cb + jj) * 2));
                *(uint4*)(Q + sw) = make_uint4(hp[0], hp[1], hp[2], hp[3]);
            }

            asm volatile("cp.async.wait_group 0;" ::: "memory");
            BAR_ARRIVE(BFULL + s, 512);
            if (++s == 4) s = 0;
        }
        __syncthreads();
    }
}

// ---------------- launch ----------------
extern "C" void kernel_launch(void* const* d_in, const int* in_sizes, int n_in,
                              void* d_out, int out_size) {
    const float* x  = (const float*)d_in[0];
    const int* adj  = (const int*)d_in[1];
    const float* W  = (const float*)d_in[2];
    const float* a  = (const float*)d_in[3];
    float* out = (float*)d_out;

    cudaFuncSetAttribute(attn_mma_kernel, cudaFuncAttributeMaxDynamicSharedMemorySize, SM_TOTAL);

    prep_kernel<<<2048, 256>>>(W, adj);
    gemm_h_kernel<<<dim3(NN / 64, NH), 128>>>(x, a);
    attn_mma_kernel<<<dim3(NN / 128, NH), 512, SM_TOTAL>>>(out);
}